// round 3
// baseline (speedup 1.0000x reference)
#include <cuda_runtime.h>
#include <cuda_bf16.h>

#define N_NODES 50000
#define N_EDGES 800000
#define E_TOT   (N_EDGES + N_NODES)   // 850000 (self-loops appended)
#define IN_CH   128
#define HC      128                    // HEADS*OUT_CH
#define HEADS   2
#define OUT_CH  64
#define NEG_SLOPE 0.2f

// ---------------- scratch (static device memory; no allocations) -------------
__device__ float4 g_xh4[N_NODES * (HC / 4)];    // projected features [N,32 x float4]
__device__ float4 g_agg4[N_NODES * (HC / 4)];   // aggregated msgs    [N,32 x float4]
__device__ float  g_al[N_NODES * HEADS];        // alpha_l per node   [N,2]
__device__ float  g_ar[N_NODES * HEADS];        // alpha_r per node   [N,2]
__device__ int    g_cnt[N_NODES];               // per-dst degree (incl self-loop)
__device__ int    g_ptr[N_NODES + 1];           // CSR row pointers
__device__ int    g_cursor[N_NODES];            // scatter cursors
__device__ int    g_srcs[E_TOT];                // CSR: src node per slot

__device__ __forceinline__ float leaky(float v) {
    return v > 0.0f ? v : NEG_SLOPE * v;
}

// ================= GEMM1: xh = x @ Wl   ([N,128]x[128,128]) =================
__global__ void k_gemm_xh(const float* __restrict__ x,
                          const float* __restrict__ Wl) {
    __shared__ float  As[16][65];
    __shared__ float4 Bs[16][32];

    const int tid = threadIdx.x;
    const int tn = tid & 31;
    const int tm = tid >> 5;
    const int row0 = blockIdx.x * 64;

    float acc[8][4];
#pragma unroll
    for (int i = 0; i < 8; i++)
#pragma unroll
        for (int j = 0; j < 4; j++) acc[i][j] = 0.0f;

    const float4* x4  = (const float4*)x;
    const float4* Wl4 = (const float4*)Wl;

    for (int k0 = 0; k0 < IN_CH; k0 += 16) {
        {
            int r  = tid >> 2;
            int kc = (tid & 3) * 4;
            int grow = row0 + r;
            float4 v = make_float4(0.f, 0.f, 0.f, 0.f);
            if (grow < N_NODES)
                v = x4[(size_t)grow * (IN_CH / 4) + (k0 + kc) / 4];
            As[kc + 0][r] = v.x; As[kc + 1][r] = v.y;
            As[kc + 2][r] = v.z; As[kc + 3][r] = v.w;
        }
        {
            int kr = tid >> 4;
            int c4 = (tid & 15) * 2;
            Bs[kr][c4]     = Wl4[(size_t)(k0 + kr) * (HC / 4) + c4];
            Bs[kr][c4 + 1] = Wl4[(size_t)(k0 + kr) * (HC / 4) + c4 + 1];
        }
        __syncthreads();
#pragma unroll
        for (int k = 0; k < 16; k++) {
            float4 b = Bs[k][tn];
#pragma unroll
            for (int i = 0; i < 8; i++) {
                float a = As[k][tm * 8 + i];
                acc[i][0] += a * b.x; acc[i][1] += a * b.y;
                acc[i][2] += a * b.z; acc[i][3] += a * b.w;
            }
        }
        __syncthreads();
    }
#pragma unroll
    for (int i = 0; i < 8; i++) {
        int grow = row0 + tm * 8 + i;
        if (grow < N_NODES)
            g_xh4[(size_t)grow * 32 + tn] =
                make_float4(acc[i][0], acc[i][1], acc[i][2], acc[i][3]);
    }
}

// ========= attention dots ====================================================
__global__ void k_att_dots(const float* __restrict__ att_l,
                           const float* __restrict__ att_r) {
    int idx = blockIdx.x * blockDim.x + threadIdx.x;   // node*2 + h
    if (idx >= N_NODES * HEADS) return;
    int node = idx >> 1, h = idx & 1;
    const float4* row = &g_xh4[(size_t)node * 32 + h * 16];
    const float4* al4 = (const float4*)&att_l[h * OUT_CH];
    const float4* ar4 = (const float4*)&att_r[h * OUT_CH];
    float sl = 0.f, sr = 0.f;
#pragma unroll
    for (int c = 0; c < 16; c++) {
        float4 v = row[c];
        float4 a = al4[c];
        float4 r = ar4[c];
        sl += v.x * a.x + v.y * a.y + v.z * a.z + v.w * a.w;
        sr += v.x * r.x + v.y * r.y + v.z * r.z + v.w * r.w;
    }
    g_al[idx] = sl;
    g_ar[idx] = sr;
}

// ==================== CSR build: hist -> scan -> scatter =====================
__global__ void k_init_cnt() {
    int i = blockIdx.x * blockDim.x + threadIdx.x;
    if (i < N_NODES) g_cnt[i] = 1;   // self-loop baked in
}

// edge_index is int32: [src x 800000][dst x 800000]
__global__ void k_count(const int* __restrict__ ei) {
    int e = blockIdx.x * blockDim.x + threadIdx.x;
    if (e >= N_EDGES) return;
    int d = ei[N_EDGES + e];
    if (d >= 0 && d < N_NODES)       // defensive: never trap on bad dtype
        atomicAdd(&g_cnt[d], 1);
}

// single-block exclusive scan of g_cnt -> g_ptr / g_cursor (1024 threads)
__global__ void k_scan() {
    __shared__ int sm[1024];
    const int tid = threadIdx.x;
    const int CH  = (N_NODES + 1023) / 1024;   // 49
    const int base = tid * CH;
    int sum = 0;
    for (int j = 0; j < CH; j++) {
        int idx = base + j;
        if (idx < N_NODES) sum += g_cnt[idx];
    }
    sm[tid] = sum;
    __syncthreads();
    for (int off = 1; off < 1024; off <<= 1) {
        int v = 0;
        if (tid >= off) v = sm[tid - off];
        __syncthreads();
        if (tid >= off) sm[tid] += v;
        __syncthreads();
    }
    int run = sm[tid] - sum;
    for (int j = 0; j < CH; j++) {
        int idx = base + j;
        if (idx < N_NODES) {
            g_ptr[idx] = run;
            g_cursor[idx] = run;
            run += g_cnt[idx];
        }
    }
    if (tid == 1023) g_ptr[N_NODES] = run;
}

__global__ void k_scatter(const int* __restrict__ ei) {
    int e = blockIdx.x * blockDim.x + threadIdx.x;
    if (e >= E_TOT) return;
    int s, d;
    if (e < N_EDGES) { s = ei[e]; d = ei[N_EDGES + e]; }
    else             { s = e - N_EDGES; d = s; }         // self-loop
    if (s < 0 || s >= N_NODES || d < 0 || d >= N_NODES) return;  // defensive
    int pos = atomicAdd(&g_cursor[d], 1);
    g_srcs[pos] = s;
}

// ============ per-dst segment softmax + weighted gather (warp/node) ==========
__global__ void k_aggregate() {
    const int warp = (blockIdx.x * blockDim.x + threadIdx.x) >> 5;
    const int lane = threadIdx.x & 31;
    if (warp >= N_NODES) return;
    const int i = warp;
    const int start = g_ptr[i], end = g_ptr[i + 1];

    const float ar0 = g_ar[2 * i], ar1 = g_ar[2 * i + 1];

    float m0 = -1e30f, m1 = -1e30f, s0 = 0.f, s1 = 0.f;
    for (int e = start + lane; e < end; e += 32) {
        int s = g_srcs[e];
        float e0 = leaky(g_al[2 * s]     + ar0);
        float e1 = leaky(g_al[2 * s + 1] + ar1);
        float nm0 = fmaxf(m0, e0);
        s0 = s0 * __expf(m0 - nm0) + __expf(e0 - nm0);
        m0 = nm0;
        float nm1 = fmaxf(m1, e1);
        s1 = s1 * __expf(m1 - nm1) + __expf(e1 - nm1);
        m1 = nm1;
    }
#pragma unroll
    for (int off = 16; off; off >>= 1) {
        float mo = __shfl_xor_sync(0xffffffffu, m0, off);
        float so = __shfl_xor_sync(0xffffffffu, s0, off);
        float nm = fmaxf(m0, mo);
        s0 = s0 * __expf(m0 - nm) + so * __expf(mo - nm);
        m0 = nm;
        mo = __shfl_xor_sync(0xffffffffu, m1, off);
        so = __shfl_xor_sync(0xffffffffu, s1, off);
        nm = fmaxf(m1, mo);
        s1 = s1 * __expf(m1 - nm) + so * __expf(mo - nm);
        m1 = nm;
    }
    const int h   = (lane >= 16) ? 1 : 0;
    const float arh  = h ? ar1 : ar0;
    const float mh   = h ? m1  : m0;
    const float invh = 1.0f / ((h ? s1 : s0) + 1e-16f);

    float4 acc = make_float4(0.f, 0.f, 0.f, 0.f);
    for (int e = start; e < end; e++) {
        int s = g_srcs[e];
        float alh = g_al[2 * s + h];
        float w = __expf(leaky(alh + arh) - mh) * invh;
        float4 v = g_xh4[(size_t)s * 32 + lane];
        acc.x += w * v.x; acc.y += w * v.y;
        acc.z += w * v.z; acc.w += w * v.w;
    }
    g_agg4[(size_t)i * 32 + lane] = acc;
}

// ============ GEMM2: out = agg @ Wout + bias  ([N,128]x[128,64]) =============
__global__ void k_gemm_out(const float* __restrict__ Wout,
                           const float* __restrict__ bias,
                           float* __restrict__ out) {
    __shared__ float  As[16][65];
    __shared__ float4 Bs[16][16];

    const int tid = threadIdx.x;
    const int tn = tid & 15;
    const int tm = tid >> 4;
    const int row0 = blockIdx.x * 64;

    float acc[4][4];
#pragma unroll
    for (int i = 0; i < 4; i++)
#pragma unroll
        for (int j = 0; j < 4; j++) acc[i][j] = 0.0f;

    const float4* W4 = (const float4*)Wout;

    for (int k0 = 0; k0 < HC; k0 += 16) {
        {
            int r  = tid >> 2;
            int kc = (tid & 3) * 4;
            int grow = row0 + r;
            float4 v = make_float4(0.f, 0.f, 0.f, 0.f);
            if (grow < N_NODES)
                v = g_agg4[(size_t)grow * 32 + (k0 + kc) / 4];
            As[kc + 0][r] = v.x; As[kc + 1][r] = v.y;
            As[kc + 2][r] = v.z; As[kc + 3][r] = v.w;
        }
        {
            int kr = tid >> 4;
            int c4 = tid & 15;
            Bs[kr][c4] = W4[(size_t)(k0 + kr) * (OUT_CH / 4) + c4];
        }
        __syncthreads();
#pragma unroll
        for (int k = 0; k < 16; k++) {
            float4 b = Bs[k][tn];
#pragma unroll
            for (int i = 0; i < 4; i++) {
                float a = As[k][tm * 4 + i];
                acc[i][0] += a * b.x; acc[i][1] += a * b.y;
                acc[i][2] += a * b.z; acc[i][3] += a * b.w;
            }
        }
        __syncthreads();
    }
    const float4* b4 = (const float4*)bias;
    float4 bv = b4[tn];
    float4* out4 = (float4*)out;
#pragma unroll
    for (int i = 0; i < 4; i++) {
        int grow = row0 + tm * 4 + i;
        if (grow < N_NODES) {
            float4 r;
            r.x = acc[i][0] + bv.x; r.y = acc[i][1] + bv.y;
            r.z = acc[i][2] + bv.z; r.w = acc[i][3] + bv.w;
            out4[(size_t)grow * (OUT_CH / 4) + tn] = r;
        }
    }
}

// ============================== launch ======================================
extern "C" void kernel_launch(void* const* d_in, const int* in_sizes, int n_in,
                              void* d_out, int out_size) {
    const float* x     = (const float*)d_in[0];
    const int*   ei    = (const int*)d_in[1];     // int32 edge_index (JAX x64 off)
    const float* Wl    = (const float*)d_in[2];
    const float* att_l = (const float*)d_in[3];
    const float* att_r = (const float*)d_in[4];
    const float* Wout  = (const float*)d_in[5];
    const float* bias  = (const float*)d_in[6];
    float*       out   = (float*)d_out;

    (void)in_sizes; (void)n_in; (void)out_size;

    k_gemm_xh<<<(N_NODES + 63) / 64, 256>>>(x, Wl);
    k_att_dots<<<(N_NODES * HEADS + 255) / 256, 256>>>(att_l, att_r);
    k_init_cnt<<<(N_NODES + 255) / 256, 256>>>();
    k_count<<<(N_EDGES + 255) / 256, 256>>>(ei);
    k_scan<<<1, 1024>>>();
    k_scatter<<<(E_TOT + 255) / 256, 256>>>(ei);
    k_aggregate<<<(N_NODES * 32 + 255) / 256, 256>>>();
    k_gemm_out<<<(N_NODES + 63) / 64, 256>>>(Wout, bias, out);
}

// round 4
// speedup vs baseline: 1.0100x; 1.0100x over previous
#include <cuda_runtime.h>
#include <cuda_bf16.h>
#include <cstdint>

#define N_NODES 50000
#define N_EDGES 800000
#define E_TOT   (N_EDGES + N_NODES)   // 850000 (self-loops appended)
#define IN_CH   128
#define HC      128                    // HEADS*OUT_CH
#define HEADS   2
#define OUT_CH  64
#define NEG_SLOPE 0.2f

// ---------------- scratch (static device memory; no allocations) -------------
__device__ float4 g_xh4[N_NODES * (HC / 4)];    // projected features [N,32 x float4]
__device__ float4 g_agg4[N_NODES * (HC / 4)];   // aggregated msgs    [N,32 x float4]
__device__ float  g_al[N_NODES * HEADS];        // alpha_l per node   [N,2]
__device__ float  g_ar[N_NODES * HEADS];        // alpha_r per node   [N,2]
__device__ int    g_cnt[N_NODES];               // per-dst degree (incl self-loop)
__device__ int    g_ptr[N_NODES + 1];           // CSR row pointers
__device__ int    g_cursor[N_NODES];            // scatter cursors
__device__ int    g_srcs[E_TOT];                // CSR: src node per slot

__device__ __forceinline__ float leaky(float v) {
    return v > 0.0f ? v : NEG_SLOPE * v;
}

// ---- packed f32x2 helpers (FFMA2 path; ptxas only emits via PTX f32x2) ------
#define PACK2(d, lo, hi) \
    asm("mov.b64 %0, {%1, %2};" : "=l"(d) : "r"(__float_as_uint(lo)), "r"(__float_as_uint(hi)))
#define UNPACK2(lo, hi, s) \
    asm("mov.b64 {%0, %1}, %2;" : "=r"(lo), "=r"(hi) : "l"(s))
#define FMA2(d, a, b, c) \
    asm("fma.rn.f32x2 %0, %1, %2, %3;" : "=l"(d) : "l"(a), "l"(b), "l"(c))

// ================= GEMM1: xh = x @ Wl  (+fused attention dots) ==============
// 64-row tile, 128 cols, TK=16, 256 threads, thread tile 8Mx4N (2x f32x2).
__global__ void k_gemm_xh(const float* __restrict__ x,
                          const float* __restrict__ Wl,
                          const float* __restrict__ att_l,
                          const float* __restrict__ att_r) {
    __shared__ float  As[16][65];
    __shared__ float4 Bs[16][32];

    const int tid = threadIdx.x;
    const int tn = tid & 31;        // lane -> col group (4 cols: 4tn..4tn+3)
    const int tm = tid >> 5;        // warp -> row group (8 rows)
    const int row0 = blockIdx.x * 64;

    unsigned long long a01[8], a23[8];
#pragma unroll
    for (int i = 0; i < 8; i++) { a01[i] = 0ull; a23[i] = 0ull; }

    const float4* x4  = (const float4*)x;
    const float4* Wl4 = (const float4*)Wl;

    for (int k0 = 0; k0 < IN_CH; k0 += 16) {
        {
            int r  = tid >> 2;
            int kc = (tid & 3) * 4;
            int grow = row0 + r;
            float4 v = make_float4(0.f, 0.f, 0.f, 0.f);
            if (grow < N_NODES)
                v = x4[(size_t)grow * (IN_CH / 4) + (k0 + kc) / 4];
            As[kc + 0][r] = v.x; As[kc + 1][r] = v.y;
            As[kc + 2][r] = v.z; As[kc + 3][r] = v.w;
        }
        {
            int kr = tid >> 4;
            int c4 = (tid & 15) * 2;
            Bs[kr][c4]     = Wl4[(size_t)(k0 + kr) * (HC / 4) + c4];
            Bs[kr][c4 + 1] = Wl4[(size_t)(k0 + kr) * (HC / 4) + c4 + 1];
        }
        __syncthreads();
#pragma unroll
        for (int k = 0; k < 16; k++) {
            float4 b = Bs[k][tn];
            unsigned long long b01, b23;
            PACK2(b01, b.x, b.y);
            PACK2(b23, b.z, b.w);
#pragma unroll
            for (int i = 0; i < 8; i++) {
                float a = As[k][tm * 8 + i];
                unsigned long long a2;
                PACK2(a2, a, a);
                FMA2(a01[i], a2, b01, a01[i]);
                FMA2(a23[i], a2, b23, a23[i]);
            }
        }
        __syncthreads();
    }

    // epilogue: store xh + fused attention dot-products.
    // col layout: global col = h*64 + c, att flat index == global col.
    float4 attl = ((const float4*)att_l)[tn];
    float4 attr = ((const float4*)att_r)[tn];
#pragma unroll
    for (int i = 0; i < 8; i++) {
        unsigned int lo, hi;
        float4 v;
        UNPACK2(lo, hi, a01[i]); v.x = __uint_as_float(lo); v.y = __uint_as_float(hi);
        UNPACK2(lo, hi, a23[i]); v.z = __uint_as_float(lo); v.w = __uint_as_float(hi);

        float pl = v.x * attl.x + v.y * attl.y + v.z * attl.z + v.w * attl.w;
        float pr = v.x * attr.x + v.y * attr.y + v.z * attr.z + v.w * attr.w;
#pragma unroll
        for (int off = 8; off; off >>= 1) {      // reduce within 16-lane half (one head)
            pl += __shfl_xor_sync(0xffffffffu, pl, off);
            pr += __shfl_xor_sync(0xffffffffu, pr, off);
        }
        int grow = row0 + tm * 8 + i;
        if (grow < N_NODES) {
            g_xh4[(size_t)grow * 32 + tn] = v;
            if ((tn & 15) == 0) {
                int h = tn >> 4;
                g_al[2 * grow + h] = pl;
                g_ar[2 * grow + h] = pr;
            }
        }
    }
}

// ==================== CSR build: hist -> scan -> scatter =====================
__global__ void k_init_cnt() {
    int i = blockIdx.x * blockDim.x + threadIdx.x;
    if (i < N_NODES) g_cnt[i] = 1;   // self-loop baked in
}

// 4 edges per thread (int4) for MLP over the 318-cyc ATOMG latency.
__global__ void k_count(const int* __restrict__ ei) {
    int t = blockIdx.x * blockDim.x + threadIdx.x;
    if (t >= N_EDGES / 4) return;
    int4 d = ((const int4*)(ei + N_EDGES))[t];
    if ((unsigned)d.x < N_NODES) atomicAdd(&g_cnt[d.x], 1);
    if ((unsigned)d.y < N_NODES) atomicAdd(&g_cnt[d.y], 1);
    if ((unsigned)d.z < N_NODES) atomicAdd(&g_cnt[d.z], 1);
    if ((unsigned)d.w < N_NODES) atomicAdd(&g_cnt[d.w], 1);
}

// single-block exclusive scan of g_cnt -> g_ptr / g_cursor (1024 threads)
__global__ void k_scan() {
    __shared__ int sm[1024];
    const int tid = threadIdx.x;
    const int CH  = (N_NODES + 1023) / 1024;   // 49
    const int base = tid * CH;
    int sum = 0;
    for (int j = 0; j < CH; j++) {
        int idx = base + j;
        if (idx < N_NODES) sum += g_cnt[idx];
    }
    sm[tid] = sum;
    __syncthreads();
    for (int off = 1; off < 1024; off <<= 1) {
        int v = 0;
        if (tid >= off) v = sm[tid - off];
        __syncthreads();
        if (tid >= off) sm[tid] += v;
        __syncthreads();
    }
    int run = sm[tid] - sum;
    for (int j = 0; j < CH; j++) {
        int idx = base + j;
        if (idx < N_NODES) {
            g_ptr[idx] = run;
            g_cursor[idx] = run;
            run += g_cnt[idx];
        }
    }
    if (tid == 1023) g_ptr[N_NODES] = run;
}

// 4 edges/thread + self-loop tail threads.
__global__ void k_scatter(const int* __restrict__ ei) {
    const int NE4 = N_EDGES / 4;
    int t = blockIdx.x * blockDim.x + threadIdx.x;
    if (t < NE4) {
        int4 s = ((const int4*)ei)[t];
        int4 d = ((const int4*)(ei + N_EDGES))[t];
        if ((unsigned)s.x < N_NODES && (unsigned)d.x < N_NODES)
            g_srcs[atomicAdd(&g_cursor[d.x], 1)] = s.x;
        if ((unsigned)s.y < N_NODES && (unsigned)d.y < N_NODES)
            g_srcs[atomicAdd(&g_cursor[d.y], 1)] = s.y;
        if ((unsigned)s.z < N_NODES && (unsigned)d.z < N_NODES)
            g_srcs[atomicAdd(&g_cursor[d.z], 1)] = s.z;
        if ((unsigned)s.w < N_NODES && (unsigned)d.w < N_NODES)
            g_srcs[atomicAdd(&g_cursor[d.w], 1)] = s.w;
    } else {
        int n = t - NE4;                      // self-loop per node
        if (n < N_NODES)
            g_srcs[atomicAdd(&g_cursor[n], 1)] = n;
    }
}

// ============ per-dst segment softmax + weighted gather (warp/node) ==========
__global__ void k_aggregate() {
    const int warp = (blockIdx.x * blockDim.x + threadIdx.x) >> 5;
    const int lane = threadIdx.x & 31;
    if (warp >= N_NODES) return;
    const int i = warp;
    const int start = g_ptr[i], end = g_ptr[i + 1];

    const float ar0 = g_ar[2 * i], ar1 = g_ar[2 * i + 1];

    // pass 1: online softmax stats, lane-strided
    float m0 = -1e30f, m1 = -1e30f, s0 = 0.f, s1 = 0.f;
    for (int e = start + lane; e < end; e += 32) {
        int s = g_srcs[e];
        float e0 = leaky(g_al[2 * s]     + ar0);
        float e1 = leaky(g_al[2 * s + 1] + ar1);
        float nm0 = fmaxf(m0, e0);
        s0 = s0 * __expf(m0 - nm0) + __expf(e0 - nm0);
        m0 = nm0;
        float nm1 = fmaxf(m1, e1);
        s1 = s1 * __expf(m1 - nm1) + __expf(e1 - nm1);
        m1 = nm1;
    }
#pragma unroll
    for (int off = 16; off; off >>= 1) {
        float mo = __shfl_xor_sync(0xffffffffu, m0, off);
        float so = __shfl_xor_sync(0xffffffffu, s0, off);
        float nm = fmaxf(m0, mo);
        s0 = s0 * __expf(m0 - nm) + so * __expf(mo - nm);
        m0 = nm;
        mo = __shfl_xor_sync(0xffffffffu, m1, off);
        so = __shfl_xor_sync(0xffffffffu, s1, off);
        nm = fmaxf(m1, mo);
        s1 = s1 * __expf(m1 - nm) + so * __expf(mo - nm);
        m1 = nm;
    }
    const float inv0 = 1.0f / (s0 + 1e-16f);
    const float inv1 = 1.0f / (s1 + 1e-16f);
    const int h = (lane >= 16) ? 1 : 0;

    // pass 2: 32-edge chunks. Each lane owns one edge (coalesced src load +
    // one weight computation), then the warp broadcasts (s, w0, w1) and
    // streams 32 independent coalesced 512B gathers of xh.
    float4 acc = make_float4(0.f, 0.f, 0.f, 0.f);
    for (int eb = start; eb < end; eb += 32) {
        int e = eb + lane;
        int sm_ = 0;
        float w0 = 0.f, w1 = 0.f;
        if (e < end) {
            sm_ = g_srcs[e];
            float a0 = g_al[2 * sm_];
            float a1 = g_al[2 * sm_ + 1];
            w0 = __expf(leaky(a0 + ar0) - m0) * inv0;
            w1 = __expf(leaky(a1 + ar1) - m1) * inv1;
        }
        int cnt = min(32, end - eb);
#pragma unroll 4
        for (int j = 0; j < cnt; j++) {
            int   sj = __shfl_sync(0xffffffffu, sm_, j);
            float wl = __shfl_sync(0xffffffffu, w0, j);
            float wh = __shfl_sync(0xffffffffu, w1, j);
            float wj = h ? wh : wl;
            float4 v = g_xh4[(size_t)sj * 32 + lane];
            acc.x += wj * v.x; acc.y += wj * v.y;
            acc.z += wj * v.z; acc.w += wj * v.w;
        }
    }
    g_agg4[(size_t)i * 32 + lane] = acc;
}

// ============ GEMM2: out = agg @ Wout + bias  ([N,128]x[128,64]) =============
// 64 rows x 64 cols, TK=16, 256 threads, thread tile 4Mx4N (2x f32x2).
__global__ void k_gemm_out(const float* __restrict__ Wout,
                           const float* __restrict__ bias,
                           float* __restrict__ out) {
    __shared__ float  As[16][65];
    __shared__ float4 Bs[16][16];

    const int tid = threadIdx.x;
    const int tn = tid & 15;
    const int tm = tid >> 4;
    const int row0 = blockIdx.x * 64;

    unsigned long long a01[4], a23[4];
#pragma unroll
    for (int i = 0; i < 4; i++) { a01[i] = 0ull; a23[i] = 0ull; }

    const float4* W4 = (const float4*)Wout;

    for (int k0 = 0; k0 < HC; k0 += 16) {
        {
            int r  = tid >> 2;
            int kc = (tid & 3) * 4;
            int grow = row0 + r;
            float4 v = make_float4(0.f, 0.f, 0.f, 0.f);
            if (grow < N_NODES)
                v = g_agg4[(size_t)grow * 32 + (k0 + kc) / 4];
            As[kc + 0][r] = v.x; As[kc + 1][r] = v.y;
            As[kc + 2][r] = v.z; As[kc + 3][r] = v.w;
        }
        {
            int kr = tid >> 4;
            int c4 = tid & 15;
            Bs[kr][c4] = W4[(size_t)(k0 + kr) * (OUT_CH / 4) + c4];
        }
        __syncthreads();
#pragma unroll
        for (int k = 0; k < 16; k++) {
            float4 b = Bs[k][tn];
            unsigned long long b01, b23;
            PACK2(b01, b.x, b.y);
            PACK2(b23, b.z, b.w);
#pragma unroll
            for (int i = 0; i < 4; i++) {
                float a = As[k][tm * 4 + i];
                unsigned long long a2;
                PACK2(a2, a, a);
                FMA2(a01[i], a2, b01, a01[i]);
                FMA2(a23[i], a2, b23, a23[i]);
            }
        }
        __syncthreads();
    }
    const float4* b4 = (const float4*)bias;
    float4 bv = b4[tn];
    float4* out4 = (float4*)out;
#pragma unroll
    for (int i = 0; i < 4; i++) {
        int grow = row0 + tm * 4 + i;
        if (grow < N_NODES) {
            unsigned int lo, hi;
            float4 r;
            UNPACK2(lo, hi, a01[i]); r.x = __uint_as_float(lo) + bv.x; r.y = __uint_as_float(hi) + bv.y;
            UNPACK2(lo, hi, a23[i]); r.z = __uint_as_float(lo) + bv.z; r.w = __uint_as_float(hi) + bv.w;
            out4[(size_t)grow * (OUT_CH / 4) + tn] = r;
        }
    }
}

// ============================== launch ======================================
extern "C" void kernel_launch(void* const* d_in, const int* in_sizes, int n_in,
                              void* d_out, int out_size) {
    const float* x     = (const float*)d_in[0];
    const int*   ei    = (const int*)d_in[1];     // int32 edge_index
    const float* Wl    = (const float*)d_in[2];
    const float* att_l = (const float*)d_in[3];
    const float* att_r = (const float*)d_in[4];
    const float* Wout  = (const float*)d_in[5];
    const float* bias  = (const float*)d_in[6];
    float*       out   = (float*)d_out;

    (void)in_sizes; (void)n_in; (void)out_size;

    k_gemm_xh<<<(N_NODES + 63) / 64, 256>>>(x, Wl, att_l, att_r);
    k_init_cnt<<<(N_NODES + 255) / 256, 256>>>();
    k_count<<<(N_EDGES / 4 + 255) / 256, 256>>>(ei);
    k_scan<<<1, 1024>>>();
    k_scatter<<<(N_EDGES / 4 + N_NODES + 255) / 256, 256>>>(ei);
    k_aggregate<<<(N_NODES * 32 + 255) / 256, 256>>>();
    k_gemm_out<<<(N_NODES + 63) / 64, 256>>>(Wout, bias, out);
}

// round 5
// speedup vs baseline: 1.4607x; 1.4463x over previous
#include <cuda_runtime.h>
#include <cuda_bf16.h>
#include <cstdint>

#define N_NODES 50000
#define N_EDGES 800000
#define E_TOT   (N_EDGES + N_NODES)   // 850000 (self-loops appended)
#define IN_CH   128
#define HC      128                    // HEADS*OUT_CH
#define HEADS   2
#define OUT_CH  64
#define NEG_SLOPE 0.2f

#define SCAN_B  256
#define SCAN_NB ((N_NODES + SCAN_B - 1) / SCAN_B)   // 196

// ---------------- scratch (static device memory; no allocations) -------------
__device__ float4 g_xh4[N_NODES * (HC / 4)];    // projected features [N,32 x float4]
__device__ float4 g_agg4[N_NODES * (HC / 4)];   // aggregated msgs    [N,32 x float4]
__device__ float  g_al[N_NODES * HEADS];        // alpha_l per node   [N,2]
__device__ float  g_ar[N_NODES * HEADS];        // alpha_r per node   [N,2]
__device__ int    g_cnt[N_NODES];               // per-dst degree (incl self-loop)
__device__ int    g_ptr[N_NODES + 1];           // CSR row pointers
__device__ int    g_cursor[N_NODES];            // scatter cursors
__device__ int    g_srcs[E_TOT];                // CSR: src node per slot
__device__ int    g_bsum[SCAN_NB];              // per-block scan totals
__device__ int    g_boff[SCAN_NB];              // per-block scan offsets

__device__ __forceinline__ float leaky(float v) {
    return v > 0.0f ? v : NEG_SLOPE * v;
}

// ---- packed f32x2 helpers (FFMA2 path; ptxas only emits via PTX f32x2) ------
#define PACK2(d, lo, hi) \
    asm("mov.b64 %0, {%1, %2};" : "=l"(d) : "r"(__float_as_uint(lo)), "r"(__float_as_uint(hi)))
#define UNPACK2(lo, hi, s) \
    asm("mov.b64 {%0, %1}, %2;" : "=r"(lo), "=r"(hi) : "l"(s))
#define FMA2(d, a, b, c) \
    asm("fma.rn.f32x2 %0, %1, %2, %3;" : "=l"(d) : "l"(a), "l"(b), "l"(c))

// ================= GEMM1: xh = x @ Wl  (+fused attention dots) ==============
__global__ void k_gemm_xh(const float* __restrict__ x,
                          const float* __restrict__ Wl,
                          const float* __restrict__ att_l,
                          const float* __restrict__ att_r) {
    __shared__ float  As[16][65];
    __shared__ float4 Bs[16][32];

    const int tid = threadIdx.x;
    const int tn = tid & 31;
    const int tm = tid >> 5;
    const int row0 = blockIdx.x * 64;

    unsigned long long a01[8], a23[8];
#pragma unroll
    for (int i = 0; i < 8; i++) { a01[i] = 0ull; a23[i] = 0ull; }

    const float4* x4  = (const float4*)x;
    const float4* Wl4 = (const float4*)Wl;

    for (int k0 = 0; k0 < IN_CH; k0 += 16) {
        {
            int r  = tid >> 2;
            int kc = (tid & 3) * 4;
            int grow = row0 + r;
            float4 v = make_float4(0.f, 0.f, 0.f, 0.f);
            if (grow < N_NODES)
                v = x4[(size_t)grow * (IN_CH / 4) + (k0 + kc) / 4];
            As[kc + 0][r] = v.x; As[kc + 1][r] = v.y;
            As[kc + 2][r] = v.z; As[kc + 3][r] = v.w;
        }
        {
            int kr = tid >> 4;
            int c4 = (tid & 15) * 2;
            Bs[kr][c4]     = Wl4[(size_t)(k0 + kr) * (HC / 4) + c4];
            Bs[kr][c4 + 1] = Wl4[(size_t)(k0 + kr) * (HC / 4) + c4 + 1];
        }
        __syncthreads();
#pragma unroll
        for (int k = 0; k < 16; k++) {
            float4 b = Bs[k][tn];
            unsigned long long b01, b23;
            PACK2(b01, b.x, b.y);
            PACK2(b23, b.z, b.w);
#pragma unroll
            for (int i = 0; i < 8; i++) {
                float a = As[k][tm * 8 + i];
                unsigned long long a2;
                PACK2(a2, a, a);
                FMA2(a01[i], a2, b01, a01[i]);
                FMA2(a23[i], a2, b23, a23[i]);
            }
        }
        __syncthreads();
    }

    float4 attl = ((const float4*)att_l)[tn];
    float4 attr = ((const float4*)att_r)[tn];
#pragma unroll
    for (int i = 0; i < 8; i++) {
        unsigned int lo, hi;
        float4 v;
        UNPACK2(lo, hi, a01[i]); v.x = __uint_as_float(lo); v.y = __uint_as_float(hi);
        UNPACK2(lo, hi, a23[i]); v.z = __uint_as_float(lo); v.w = __uint_as_float(hi);

        float pl = v.x * attl.x + v.y * attl.y + v.z * attl.z + v.w * attl.w;
        float pr = v.x * attr.x + v.y * attr.y + v.z * attr.z + v.w * attr.w;
#pragma unroll
        for (int off = 8; off; off >>= 1) {
            pl += __shfl_xor_sync(0xffffffffu, pl, off);
            pr += __shfl_xor_sync(0xffffffffu, pr, off);
        }
        int grow = row0 + tm * 8 + i;
        if (grow < N_NODES) {
            g_xh4[(size_t)grow * 32 + tn] = v;
            if ((tn & 15) == 0) {
                int h = tn >> 4;
                g_al[2 * grow + h] = pl;
                g_ar[2 * grow + h] = pr;
            }
        }
    }
}

// ==================== CSR build: hist -> 3-phase scan -> scatter =============
__global__ void k_init_cnt() {
    int i = blockIdx.x * blockDim.x + threadIdx.x;
    if (i < N_NODES) g_cnt[i] = 1;   // self-loop baked in
}

__global__ void k_count(const int* __restrict__ ei) {
    int t = blockIdx.x * blockDim.x + threadIdx.x;
    if (t >= N_EDGES / 4) return;
    int4 d = ((const int4*)(ei + N_EDGES))[t];
    if ((unsigned)d.x < N_NODES) atomicAdd(&g_cnt[d.x], 1);
    if ((unsigned)d.y < N_NODES) atomicAdd(&g_cnt[d.y], 1);
    if ((unsigned)d.z < N_NODES) atomicAdd(&g_cnt[d.z], 1);
    if ((unsigned)d.w < N_NODES) atomicAdd(&g_cnt[d.w], 1);
}

// Phase A: per-block inclusive scan of 256 counts; local-exclusive -> g_ptr,
// block total -> g_bsum.
__global__ void k_scan_a() {
    __shared__ int sm[SCAN_B];
    const int tid = threadIdx.x;
    const int idx = blockIdx.x * SCAN_B + tid;
    int v = (idx < N_NODES) ? g_cnt[idx] : 0;
    sm[tid] = v;
    __syncthreads();
#pragma unroll
    for (int off = 1; off < SCAN_B; off <<= 1) {
        int t = 0;
        if (tid >= off) t = sm[tid - off];
        __syncthreads();
        sm[tid] += t;
        __syncthreads();
    }
    if (idx < N_NODES) g_ptr[idx] = sm[tid] - v;       // local exclusive
    if (tid == SCAN_B - 1) g_bsum[blockIdx.x] = sm[tid];
}

// Phase B: single block scans the 196 block totals.
__global__ void k_scan_b() {
    __shared__ int sm[SCAN_B];
    const int tid = threadIdx.x;
    int v = (tid < SCAN_NB) ? g_bsum[tid] : 0;
    sm[tid] = v;
    __syncthreads();
#pragma unroll
    for (int off = 1; off < SCAN_B; off <<= 1) {
        int t = 0;
        if (tid >= off) t = sm[tid - off];
        __syncthreads();
        sm[tid] += t;
        __syncthreads();
    }
    if (tid < SCAN_NB) g_boff[tid] = sm[tid] - v;      // exclusive
    if (tid == SCAN_B - 1) g_ptr[N_NODES] = sm[tid];   // grand total
}

// Phase C: add block offsets; mirror into cursors.
__global__ void k_scan_c() {
    const int idx = blockIdx.x * SCAN_B + threadIdx.x;
    if (idx >= N_NODES) return;
    int p = g_ptr[idx] + g_boff[blockIdx.x];
    g_ptr[idx] = p;
    g_cursor[idx] = p;
}

__global__ void k_scatter(const int* __restrict__ ei) {
    const int NE4 = N_EDGES / 4;
    int t = blockIdx.x * blockDim.x + threadIdx.x;
    if (t < NE4) {
        int4 s = ((const int4*)ei)[t];
        int4 d = ((const int4*)(ei + N_EDGES))[t];
        if ((unsigned)s.x < N_NODES && (unsigned)d.x < N_NODES)
            g_srcs[atomicAdd(&g_cursor[d.x], 1)] = s.x;
        if ((unsigned)s.y < N_NODES && (unsigned)d.y < N_NODES)
            g_srcs[atomicAdd(&g_cursor[d.y], 1)] = s.y;
        if ((unsigned)s.z < N_NODES && (unsigned)d.z < N_NODES)
            g_srcs[atomicAdd(&g_cursor[d.z], 1)] = s.z;
        if ((unsigned)s.w < N_NODES && (unsigned)d.w < N_NODES)
            g_srcs[atomicAdd(&g_cursor[d.w], 1)] = s.w;
    } else {
        int n = t - NE4;
        if (n < N_NODES)
            g_srcs[atomicAdd(&g_cursor[n], 1)] = n;
    }
}

// ============ per-dst segment softmax + weighted gather (warp/node) ==========
__global__ void k_aggregate() {
    const int warp = (blockIdx.x * blockDim.x + threadIdx.x) >> 5;
    const int lane = threadIdx.x & 31;
    if (warp >= N_NODES) return;
    const int i = warp;
    const int start = g_ptr[i], end = g_ptr[i + 1];

    const float ar0 = g_ar[2 * i], ar1 = g_ar[2 * i + 1];

    float m0 = -1e30f, m1 = -1e30f, s0 = 0.f, s1 = 0.f;
    for (int e = start + lane; e < end; e += 32) {
        int s = g_srcs[e];
        float e0 = leaky(g_al[2 * s]     + ar0);
        float e1 = leaky(g_al[2 * s + 1] + ar1);
        float nm0 = fmaxf(m0, e0);
        s0 = s0 * __expf(m0 - nm0) + __expf(e0 - nm0);
        m0 = nm0;
        float nm1 = fmaxf(m1, e1);
        s1 = s1 * __expf(m1 - nm1) + __expf(e1 - nm1);
        m1 = nm1;
    }
#pragma unroll
    for (int off = 16; off; off >>= 1) {
        float mo = __shfl_xor_sync(0xffffffffu, m0, off);
        float so = __shfl_xor_sync(0xffffffffu, s0, off);
        float nm = fmaxf(m0, mo);
        s0 = s0 * __expf(m0 - nm) + so * __expf(mo - nm);
        m0 = nm;
        mo = __shfl_xor_sync(0xffffffffu, m1, off);
        so = __shfl_xor_sync(0xffffffffu, s1, off);
        nm = fmaxf(m1, mo);
        s1 = s1 * __expf(m1 - nm) + so * __expf(mo - nm);
        m1 = nm;
    }
    const float inv0 = 1.0f / (s0 + 1e-16f);
    const float inv1 = 1.0f / (s1 + 1e-16f);
    const int h = (lane >= 16) ? 1 : 0;

    float4 acc = make_float4(0.f, 0.f, 0.f, 0.f);
    for (int eb = start; eb < end; eb += 32) {
        int e = eb + lane;
        int sm_ = 0;
        float w0 = 0.f, w1 = 0.f;
        if (e < end) {
            sm_ = g_srcs[e];
            float a0 = g_al[2 * sm_];
            float a1 = g_al[2 * sm_ + 1];
            w0 = __expf(leaky(a0 + ar0) - m0) * inv0;
            w1 = __expf(leaky(a1 + ar1) - m1) * inv1;
        }
        int cnt = min(32, end - eb);
#pragma unroll 4
        for (int j = 0; j < cnt; j++) {
            int   sj = __shfl_sync(0xffffffffu, sm_, j);
            float wl = __shfl_sync(0xffffffffu, w0, j);
            float wh = __shfl_sync(0xffffffffu, w1, j);
            float wj = h ? wh : wl;
            float4 v = g_xh4[(size_t)sj * 32 + lane];
            acc.x += wj * v.x; acc.y += wj * v.y;
            acc.z += wj * v.z; acc.w += wj * v.w;
        }
    }
    g_agg4[(size_t)i * 32 + lane] = acc;
}

// ============ GEMM2: out = agg @ Wout + bias  ([N,128]x[128,64]) =============
__global__ void k_gemm_out(const float* __restrict__ Wout,
                           const float* __restrict__ bias,
                           float* __restrict__ out) {
    __shared__ float  As[16][65];
    __shared__ float4 Bs[16][16];

    const int tid = threadIdx.x;
    const int tn = tid & 15;
    const int tm = tid >> 4;
    const int row0 = blockIdx.x * 64;

    unsigned long long a01[4], a23[4];
#pragma unroll
    for (int i = 0; i < 4; i++) { a01[i] = 0ull; a23[i] = 0ull; }

    const float4* W4 = (const float4*)Wout;

    for (int k0 = 0; k0 < HC; k0 += 16) {
        {
            int r  = tid >> 2;
            int kc = (tid & 3) * 4;
            int grow = row0 + r;
            float4 v = make_float4(0.f, 0.f, 0.f, 0.f);
            if (grow < N_NODES)
                v = g_agg4[(size_t)grow * 32 + (k0 + kc) / 4];
            As[kc + 0][r] = v.x; As[kc + 1][r] = v.y;
            As[kc + 2][r] = v.z; As[kc + 3][r] = v.w;
        }
        {
            int kr = tid >> 4;
            int c4 = tid & 15;
            Bs[kr][c4] = W4[(size_t)(k0 + kr) * (OUT_CH / 4) + c4];
        }
        __syncthreads();
#pragma unroll
        for (int k = 0; k < 16; k++) {
            float4 b = Bs[k][tn];
            unsigned long long b01, b23;
            PACK2(b01, b.x, b.y);
            PACK2(b23, b.z, b.w);
#pragma unroll
            for (int i = 0; i < 4; i++) {
                float a = As[k][tm * 4 + i];
                unsigned long long a2;
                PACK2(a2, a, a);
                FMA2(a01[i], a2, b01, a01[i]);
                FMA2(a23[i], a2, b23, a23[i]);
            }
        }
        __syncthreads();
    }
    const float4* b4 = (const float4*)bias;
    float4 bv = b4[tn];
    float4* out4 = (float4*)out;
#pragma unroll
    for (int i = 0; i < 4; i++) {
        int grow = row0 + tm * 4 + i;
        if (grow < N_NODES) {
            unsigned int lo, hi;
            float4 r;
            UNPACK2(lo, hi, a01[i]); r.x = __uint_as_float(lo) + bv.x; r.y = __uint_as_float(hi) + bv.y;
            UNPACK2(lo, hi, a23[i]); r.z = __uint_as_float(lo) + bv.z; r.w = __uint_as_float(hi) + bv.w;
            out4[(size_t)grow * (OUT_CH / 4) + tn] = r;
        }
    }
}

// ============================== launch ======================================
extern "C" void kernel_launch(void* const* d_in, const int* in_sizes, int n_in,
                              void* d_out, int out_size) {
    const float* x     = (const float*)d_in[0];
    const int*   ei    = (const int*)d_in[1];     // int32 edge_index
    const float* Wl    = (const float*)d_in[2];
    const float* att_l = (const float*)d_in[3];
    const float* att_r = (const float*)d_in[4];
    const float* Wout  = (const float*)d_in[5];
    const float* bias  = (const float*)d_in[6];
    float*       out   = (float*)d_out;

    (void)in_sizes; (void)n_in; (void)out_size;

    k_gemm_xh<<<(N_NODES + 63) / 64, 256>>>(x, Wl, att_l, att_r);
    k_init_cnt<<<(N_NODES + 255) / 256, 256>>>();
    k_count<<<(N_EDGES / 4 + 255) / 256, 256>>>(ei);
    k_scan_a<<<SCAN_NB, SCAN_B>>>();
    k_scan_b<<<1, SCAN_B>>>();
    k_scan_c<<<SCAN_NB, SCAN_B>>>();
    k_scatter<<<(N_EDGES / 4 + N_NODES + 255) / 256, 256>>>(ei);
    k_aggregate<<<(N_NODES * 32 + 255) / 256, 256>>>();
    k_gemm_out<<<(N_NODES + 63) / 64, 256>>>(Wout, bias, out);
}

// round 6
// speedup vs baseline: 1.6156x; 1.1060x over previous
#include <cuda_runtime.h>
#include <cuda_fp16.h>
#include <cstdint>

#define N_NODES 50000
#define N_EDGES 800000
#define E_TOT   (N_EDGES + N_NODES)   // 850000 (self-loops appended)
#define IN_CH   128
#define HC      128                    // HEADS*OUT_CH
#define HEADS   2
#define OUT_CH  64
#define NEG_SLOPE 0.2f

#define SCAN_B  256
#define SCAN_NB ((N_NODES + SCAN_B - 1) / SCAN_B)   // 196
#define GEMM1_BLOCKS ((N_NODES + 63) / 64)          // 782
#define COUNT_BLOCKS ((N_EDGES / 4 + 255) / 256)    // 782

// ---------------- scratch (static device memory; no allocations) -------------
__device__ uint2  g_xhh[N_NODES * 32];          // fp16 xh [N][64 x half2] (256B/row)
__device__ float4 g_agg4[N_NODES * (HC / 4)];   // aggregated msgs fp32 [N,32 x float4]
__device__ float2 g_al2[N_NODES];               // (alpha_l h0, h1) per node
__device__ float2 g_ar2[N_NODES];               // (alpha_r h0, h1) per node
__device__ int    g_cnt[N_NODES];               // zero-init; delta counts (self-loop implicit)
__device__ int    g_ptr[N_NODES + 1];           // CSR row pointers
__device__ int    g_cursor[N_NODES];            // scatter cursors
__device__ int    g_srcs[E_TOT];                // CSR: src node per slot
__device__ int    g_bsum[SCAN_NB];              // per-block scan totals

__device__ __forceinline__ float leaky(float v) {
    return v > 0.0f ? v : NEG_SLOPE * v;
}

// ---- packed f32x2 helpers (FFMA2 path; ptxas only emits via PTX f32x2) ------
#define PACK2(d, lo, hi) \
    asm("mov.b64 %0, {%1, %2};" : "=l"(d) : "r"(__float_as_uint(lo)), "r"(__float_as_uint(hi)))
#define UNPACK2(lo, hi, s) \
    asm("mov.b64 {%0, %1}, %2;" : "=r"(lo), "=r"(hi) : "l"(s))
#define FMA2(d, a, b, c) \
    asm("fma.rn.f32x2 %0, %1, %2, %3;" : "=l"(d) : "l"(a), "l"(b), "l"(c))

// ========== MEGA1: [GEMM1 blocks | edge-count blocks], independent ===========
// GEMM1: xh = x @ Wl (64-row tile, 128 cols, TK=16, 8Mx4N f32x2) + fused
//        attention dots from fp32 accumulators; xh stored as fp16.
// COUNT: per-dst degree histogram (4 edges/thread, int4 loads).
__global__ void k_mega1(const float* __restrict__ x,
                        const float* __restrict__ Wl,
                        const float* __restrict__ att_l,
                        const float* __restrict__ att_r,
                        const int*   __restrict__ ei) {
    __shared__ float  As[16][65];
    __shared__ float4 Bs[16][32];

    const int tid = threadIdx.x;

    if (blockIdx.x >= GEMM1_BLOCKS) {
        // ---- histogram role ----
        int t = (blockIdx.x - GEMM1_BLOCKS) * 256 + tid;
        if (t < N_EDGES / 4) {
            int4 d = ((const int4*)(ei + N_EDGES))[t];
            if ((unsigned)d.x < N_NODES) atomicAdd(&g_cnt[d.x], 1);
            if ((unsigned)d.y < N_NODES) atomicAdd(&g_cnt[d.y], 1);
            if ((unsigned)d.z < N_NODES) atomicAdd(&g_cnt[d.z], 1);
            if ((unsigned)d.w < N_NODES) atomicAdd(&g_cnt[d.w], 1);
        }
        return;
    }

    // ---- GEMM role ----
    const int tn = tid & 31;        // lane -> col group (4 cols: 4tn..4tn+3)
    const int tm = tid >> 5;        // warp -> row group (8 rows)
    const int row0 = blockIdx.x * 64;

    unsigned long long a01[8], a23[8];
#pragma unroll
    for (int i = 0; i < 8; i++) { a01[i] = 0ull; a23[i] = 0ull; }

    const float4* x4  = (const float4*)x;
    const float4* Wl4 = (const float4*)Wl;

    for (int k0 = 0; k0 < IN_CH; k0 += 16) {
        {
            int r  = tid >> 2;
            int kc = (tid & 3) * 4;
            int grow = row0 + r;
            float4 v = make_float4(0.f, 0.f, 0.f, 0.f);
            if (grow < N_NODES)
                v = x4[(size_t)grow * (IN_CH / 4) + (k0 + kc) / 4];
            As[kc + 0][r] = v.x; As[kc + 1][r] = v.y;
            As[kc + 2][r] = v.z; As[kc + 3][r] = v.w;
        }
        {
            int kr = tid >> 4;
            int c4 = (tid & 15) * 2;
            Bs[kr][c4]     = Wl4[(size_t)(k0 + kr) * (HC / 4) + c4];
            Bs[kr][c4 + 1] = Wl4[(size_t)(k0 + kr) * (HC / 4) + c4 + 1];
        }
        __syncthreads();
#pragma unroll
        for (int k = 0; k < 16; k++) {
            float4 b = Bs[k][tn];
            unsigned long long b01, b23;
            PACK2(b01, b.x, b.y);
            PACK2(b23, b.z, b.w);
#pragma unroll
            for (int i = 0; i < 8; i++) {
                float a = As[k][tm * 8 + i];
                unsigned long long a2;
                PACK2(a2, a, a);
                FMA2(a01[i], a2, b01, a01[i]);
                FMA2(a23[i], a2, b23, a23[i]);
            }
        }
        __syncthreads();
    }

    // epilogue: fp16 xh store + fused attention dots (fp32-exact logits).
    float4 attl = ((const float4*)att_l)[tn];
    float4 attr = ((const float4*)att_r)[tn];
#pragma unroll
    for (int i = 0; i < 8; i++) {
        unsigned int lo, hi;
        float4 v;
        UNPACK2(lo, hi, a01[i]); v.x = __uint_as_float(lo); v.y = __uint_as_float(hi);
        UNPACK2(lo, hi, a23[i]); v.z = __uint_as_float(lo); v.w = __uint_as_float(hi);

        float pl = v.x * attl.x + v.y * attl.y + v.z * attl.z + v.w * attl.w;
        float pr = v.x * attr.x + v.y * attr.y + v.z * attr.z + v.w * attr.w;
#pragma unroll
        for (int off = 8; off; off >>= 1) {      // reduce within 16-lane half (one head)
            pl += __shfl_xor_sync(0xffffffffu, pl, off);
            pr += __shfl_xor_sync(0xffffffffu, pr, off);
        }
        float pl1 = __shfl_sync(0xffffffffu, pl, 16);   // head-1 totals (lane 16)
        float pr1 = __shfl_sync(0xffffffffu, pr, 16);

        int grow = row0 + tm * 8 + i;
        if (grow < N_NODES) {
            __half2 h01 = __floats2half2_rn(v.x, v.y);
            __half2 h23 = __floats2half2_rn(v.z, v.w);
            uint2 pk;
            pk.x = *reinterpret_cast<unsigned*>(&h01);
            pk.y = *reinterpret_cast<unsigned*>(&h23);
            g_xhh[(size_t)grow * 32 + tn] = pk;
            if (tn == 0) {
                g_al2[grow] = make_float2(pl, pl1);
                g_ar2[grow] = make_float2(pr, pr1);
            }
        }
    }
}

// Phase A: per-block scan of (cnt+1); resets cnt for the next graph replay.
__global__ void k_scan_a() {
    __shared__ int sm[SCAN_B];
    const int tid = threadIdx.x;
    const int idx = blockIdx.x * SCAN_B + tid;
    int v = 0;
    if (idx < N_NODES) {
        v = g_cnt[idx] + 1;      // +1 = self-loop
        g_cnt[idx] = 0;          // re-arm for next replay
    }
    sm[tid] = v;
    __syncthreads();
#pragma unroll
    for (int off = 1; off < SCAN_B; off <<= 1) {
        int t = 0;
        if (tid >= off) t = sm[tid - off];
        __syncthreads();
        sm[tid] += t;
        __syncthreads();
    }
    if (idx < N_NODES) g_ptr[idx] = sm[tid] - v;       // local exclusive
    if (tid == SCAN_B - 1) g_bsum[blockIdx.x] = sm[tid];
}

// Phase BC: each block reduces bsum[0..blk-1] itself (196 ints from L2),
// then applies the offset. One launch instead of two.
__global__ void k_scan_bc() {
    __shared__ int red[SCAN_B];
    const int tid = threadIdx.x;
    const int b   = blockIdx.x;
    red[tid] = (tid < SCAN_NB && tid < b) ? g_bsum[tid] : 0;
    __syncthreads();
#pragma unroll
    for (int off = SCAN_B / 2; off; off >>= 1) {
        if (tid < off) red[tid] += red[tid + off];
        __syncthreads();
    }
    const int off0 = red[0];
    const int idx = b * SCAN_B + tid;
    if (idx < N_NODES) {
        int p = g_ptr[idx] + off0;
        g_ptr[idx] = p;
        g_cursor[idx] = p;
    }
    if (b == SCAN_NB - 1 && tid == 0)
        g_ptr[N_NODES] = off0 + g_bsum[SCAN_NB - 1];
}

// 4 edges/thread + self-loop tail threads.
__global__ void k_scatter(const int* __restrict__ ei) {
    const int NE4 = N_EDGES / 4;
    int t = blockIdx.x * blockDim.x + threadIdx.x;
    if (t < NE4) {
        int4 s = ((const int4*)ei)[t];
        int4 d = ((const int4*)(ei + N_EDGES))[t];
        if ((unsigned)s.x < N_NODES && (unsigned)d.x < N_NODES)
            g_srcs[atomicAdd(&g_cursor[d.x], 1)] = s.x;
        if ((unsigned)s.y < N_NODES && (unsigned)d.y < N_NODES)
            g_srcs[atomicAdd(&g_cursor[d.y], 1)] = s.y;
        if ((unsigned)s.z < N_NODES && (unsigned)d.z < N_NODES)
            g_srcs[atomicAdd(&g_cursor[d.z], 1)] = s.z;
        if ((unsigned)s.w < N_NODES && (unsigned)d.w < N_NODES)
            g_srcs[atomicAdd(&g_cursor[d.w], 1)] = s.w;
    } else {
        int n = t - NE4;
        if (n < N_NODES)
            g_srcs[atomicAdd(&g_cursor[n], 1)] = n;
    }
}

// ============ per-dst segment softmax + weighted gather (warp/node) ==========
__global__ void k_aggregate() {
    const int warp = (blockIdx.x * blockDim.x + threadIdx.x) >> 5;
    const int lane = threadIdx.x & 31;
    if (warp >= N_NODES) return;
    const int i = warp;
    const int start = g_ptr[i], end = g_ptr[i + 1];

    const float2 ar = g_ar2[i];

    // pass 1: online softmax stats, lane-strided (one float2 gather per edge)
    float m0 = -1e30f, m1 = -1e30f, s0 = 0.f, s1 = 0.f;
    for (int e = start + lane; e < end; e += 32) {
        int s = g_srcs[e];
        float2 al = g_al2[s];
        float e0 = leaky(al.x + ar.x);
        float e1 = leaky(al.y + ar.y);
        float nm0 = fmaxf(m0, e0);
        s0 = s0 * __expf(m0 - nm0) + __expf(e0 - nm0);
        m0 = nm0;
        float nm1 = fmaxf(m1, e1);
        s1 = s1 * __expf(m1 - nm1) + __expf(e1 - nm1);
        m1 = nm1;
    }
#pragma unroll
    for (int off = 16; off; off >>= 1) {
        float mo = __shfl_xor_sync(0xffffffffu, m0, off);
        float so = __shfl_xor_sync(0xffffffffu, s0, off);
        float nm = fmaxf(m0, mo);
        s0 = s0 * __expf(m0 - nm) + so * __expf(mo - nm);
        m0 = nm;
        mo = __shfl_xor_sync(0xffffffffu, m1, off);
        so = __shfl_xor_sync(0xffffffffu, s1, off);
        nm = fmaxf(m1, mo);
        s1 = s1 * __expf(m1 - nm) + so * __expf(mo - nm);
        m1 = nm;
    }
    const float inv0 = 1.0f / (s0 + 1e-16f);
    const float inv1 = 1.0f / (s1 + 1e-16f);
    const int h = (lane >= 16) ? 1 : 0;

    // pass 2: 32-edge chunks; lane owns one edge's weight, warp broadcasts and
    // streams 32 independent coalesced 256B fp16 gathers.
    float4 acc = make_float4(0.f, 0.f, 0.f, 0.f);
    for (int eb = start; eb < end; eb += 32) {
        int e = eb + lane;
        int sm_ = 0;
        float w0 = 0.f, w1 = 0.f;
        if (e < end) {
            sm_ = g_srcs[e];
            float2 al = g_al2[sm_];
            w0 = __expf(leaky(al.x + ar.x) - m0) * inv0;
            w1 = __expf(leaky(al.y + ar.y) - m1) * inv1;
        }
        int cnt = min(32, end - eb);
#pragma unroll 4
        for (int j = 0; j < cnt; j++) {
            int   sj = __shfl_sync(0xffffffffu, sm_, j);
            float wl = __shfl_sync(0xffffffffu, w0, j);
            float wh = __shfl_sync(0xffffffffu, w1, j);
            float wj = h ? wh : wl;
            uint2 p = g_xhh[(size_t)sj * 32 + lane];
            __half2 h01 = *reinterpret_cast<__half2*>(&p.x);
            __half2 h23 = *reinterpret_cast<__half2*>(&p.y);
            float2 f01 = __half22float2(h01);
            float2 f23 = __half22float2(h23);
            acc.x += wj * f01.x; acc.y += wj * f01.y;
            acc.z += wj * f23.x; acc.w += wj * f23.y;
        }
    }
    g_agg4[(size_t)i * 32 + lane] = acc;
}

// ============ GEMM2: out = agg @ Wout + bias  ([N,128]x[128,64]) =============
__global__ void k_gemm_out(const float* __restrict__ Wout,
                           const float* __restrict__ bias,
                           float* __restrict__ out) {
    __shared__ float  As[16][65];
    __shared__ float4 Bs[16][16];

    const int tid = threadIdx.x;
    const int tn = tid & 15;
    const int tm = tid >> 4;
    const int row0 = blockIdx.x * 64;

    unsigned long long a01[4], a23[4];
#pragma unroll
    for (int i = 0; i < 4; i++) { a01[i] = 0ull; a23[i] = 0ull; }

    const float4* W4 = (const float4*)Wout;

    for (int k0 = 0; k0 < HC; k0 += 16) {
        {
            int r  = tid >> 2;
            int kc = (tid & 3) * 4;
            int grow = row0 + r;
            float4 v = make_float4(0.f, 0.f, 0.f, 0.f);
            if (grow < N_NODES)
                v = g_agg4[(size_t)grow * 32 + (k0 + kc) / 4];
            As[kc + 0][r] = v.x; As[kc + 1][r] = v.y;
            As[kc + 2][r] = v.z; As[kc + 3][r] = v.w;
        }
        {
            int kr = tid >> 4;
            int c4 = tid & 15;
            Bs[kr][c4] = W4[(size_t)(k0 + kr) * (OUT_CH / 4) + c4];
        }
        __syncthreads();
#pragma unroll
        for (int k = 0; k < 16; k++) {
            float4 b = Bs[k][tn];
            unsigned long long b01, b23;
            PACK2(b01, b.x, b.y);
            PACK2(b23, b.z, b.w);
#pragma unroll
            for (int i = 0; i < 4; i++) {
                float a = As[k][tm * 4 + i];
                unsigned long long a2;
                PACK2(a2, a, a);
                FMA2(a01[i], a2, b01, a01[i]);
                FMA2(a23[i], a2, b23, a23[i]);
            }
        }
        __syncthreads();
    }
    const float4* b4 = (const float4*)bias;
    float4 bv = b4[tn];
    float4* out4 = (float4*)out;
#pragma unroll
    for (int i = 0; i < 4; i++) {
        int grow = row0 + tm * 4 + i;
        if (grow < N_NODES) {
            unsigned int lo, hi;
            float4 r;
            UNPACK2(lo, hi, a01[i]); r.x = __uint_as_float(lo) + bv.x; r.y = __uint_as_float(hi) + bv.y;
            UNPACK2(lo, hi, a23[i]); r.z = __uint_as_float(lo) + bv.z; r.w = __uint_as_float(hi) + bv.w;
            out4[(size_t)grow * (OUT_CH / 4) + tn] = r;
        }
    }
}

// ============================== launch ======================================
extern "C" void kernel_launch(void* const* d_in, const int* in_sizes, int n_in,
                              void* d_out, int out_size) {
    const float* x     = (const float*)d_in[0];
    const int*   ei    = (const int*)d_in[1];     // int32 edge_index
    const float* Wl    = (const float*)d_in[2];
    const float* att_l = (const float*)d_in[3];
    const float* att_r = (const float*)d_in[4];
    const float* Wout  = (const float*)d_in[5];
    const float* bias  = (const float*)d_in[6];
    float*       out   = (float*)d_out;

    (void)in_sizes; (void)n_in; (void)out_size;

    k_mega1<<<GEMM1_BLOCKS + COUNT_BLOCKS, 256>>>(x, Wl, att_l, att_r, ei);
    k_scan_a<<<SCAN_NB, SCAN_B>>>();
    k_scan_bc<<<SCAN_NB, SCAN_B>>>();
    k_scatter<<<(N_EDGES / 4 + N_NODES + 255) / 256, 256>>>(ei);
    k_aggregate<<<(N_NODES * 32 + 255) / 256, 256>>>();
    k_gemm_out<<<(N_NODES + 63) / 64, 256>>>(Wout, bias, out);
}